// round 8
// baseline (speedup 1.0000x reference)
#include <cuda_runtime.h>
#include <cuda_bf16.h>

// ---------------------------------------------------------------------------
// 2-layer GCN. Pull aggregation from fixed-capacity per-node edge buckets
// (src-only; no count/scan pass — the fill cursor IS the degree).
// tf32 tensor-core GEMMs. Bucket build overlapped with GEMM1 (fork/join).
// ---------------------------------------------------------------------------

#define NMAX   50048
#define EMAX   800000
#define INF    128
#define OUTF   64
#define CAP    96      // bucket capacity (deg ~ Poisson(16); P(>=96) ~ 1e-40)

__device__ int   g_is64;
__device__ int   g_fill[NMAX];          // cursors -> in-degree after fill
__device__ int   g_bkt [NMAX * CAP];    // per-node src lists
__device__ float g_dinv[NMAX];
__device__ float g_h1  [NMAX * INF];
__device__ float g_agg1[NMAX * INF];
__device__ float g_h2  [NMAX * OUTF];

// ---------------------------------------------------------------------------
__global__ void k_probe(const int* __restrict__ w32, int words) {
    __shared__ int viol;
    if (threadIdx.x == 0) viol = 0;
    __syncthreads();
    int nchk = words / 2;
    if (nchk > 32768) nchk = 32768;
    int bad = 0;
    for (int i = threadIdx.x; i < nchk; i += blockDim.x)
        if (w32[2 * i + 1] != 0) bad = 1;
    if (bad) atomicOr(&viol, 1);
    __syncthreads();
    if (threadIdx.x == 0) g_is64 = (viol == 0) ? 1 : 0;
}

__global__ void k_zero_fill(int n) {
    int i = blockIdx.x * blockDim.x + threadIdx.x;
    if (i < n) g_fill[i] = 0;
}

// scatter src ids into dst buckets; cursor counts degree
__global__ void k_fill(const void* __restrict__ ei, int E) {
    int e = blockIdx.x * blockDim.x + threadIdx.x;
    if (e >= E) return;
    int s, d;
    if (g_is64) {
        const long long* p = (const long long*)ei;
        s = (int)p[e];  d = (int)p[E + e];
    } else {
        const int* p = (const int*)ei;
        s = p[e];       d = p[E + e];
    }
    int pos = atomicAdd(&g_fill[d], 1);
    if (pos < CAP) g_bkt[d * CAP + pos] = s;
}

__global__ void k_dinv(int n) {
    int i = blockIdx.x * blockDim.x + threadIdx.x;
    if (i < n) g_dinv[i] = rsqrtf((float)(g_fill[i] + 1));  // +1 self loop
}

// ---------------------------------------------------------------------------
// tf32 tensor-core GEMM:  Y[M,TN] = op(X)[M,128] * W[128,TN]
// ---------------------------------------------------------------------------
__device__ __forceinline__ unsigned f2tf(float f) {
    unsigned r;
    asm("cvt.rna.tf32.f32 %0, %1;" : "=r"(r) : "f"(f));
    return r;
}

template <int TN, bool PRELU>
__global__ void k_gemm_tf32(const float* __restrict__ Xin, const float* __restrict__ W,
                            const float* __restrict__ bias_in, int M)
{
    constexpr int KC  = 32;
    constexpr int NT  = TN / 8;
    constexpr int PAD = 36;

    const float* __restrict__ X = PRELU ? (const float*)g_agg1 : Xin;
    float* __restrict__ Y       = PRELU ? g_h2 : g_h1;

    __shared__ unsigned xs[64 * PAD];
    __shared__ unsigned wt[TN * PAD];

    const int tid  = threadIdx.x;
    const int lane = tid & 31;
    const int wid  = tid >> 5;
    const int m0   = blockIdx.x * 64;
    const int mw   = wid * 16;

    float acc[NT][4];
#pragma unroll
    for (int t = 0; t < NT; t++) { acc[t][0]=acc[t][1]=acc[t][2]=acc[t][3]=0.f; }

    const int r4 = lane >> 2;
    const int c4 = lane & 3;

    for (int kc = 0; kc < 128; kc += KC) {
#pragma unroll
        for (int i = 0; i < 4; i++) {
            int idx = tid + i * 128;
            int r   = idx >> 3;
            int kv  = (idx & 7) * 4;
            int row = m0 + r;
            float4 v = make_float4(0.f, 0.f, 0.f, 0.f);
            if (row < M) v = *(const float4*)&X[row * 128 + kc + kv];
            if (PRELU) {
                float4 b = *(const float4*)&bias_in[kc + kv];
                v.x = fmaxf(v.x + b.x, 0.f);
                v.y = fmaxf(v.y + b.y, 0.f);
                v.z = fmaxf(v.z + b.z, 0.f);
                v.w = fmaxf(v.w + b.w, 0.f);
            }
            uint4 u = make_uint4(f2tf(v.x), f2tf(v.y), f2tf(v.z), f2tf(v.w));
            *(uint4*)&xs[r * PAD + kv] = u;
        }
#pragma unroll
        for (int i = 0; i < (KC * TN / 4) / 128; i++) {
            int idx = tid + i * 128;
            int kk  = idx / (TN / 4);
            int n4  = (idx % (TN / 4)) * 4;
            float4 v = *(const float4*)&W[(kc + kk) * TN + n4];
            wt[(n4 + 0) * PAD + kk] = f2tf(v.x);
            wt[(n4 + 1) * PAD + kk] = f2tf(v.y);
            wt[(n4 + 2) * PAD + kk] = f2tf(v.z);
            wt[(n4 + 3) * PAD + kk] = f2tf(v.w);
        }
        __syncthreads();

#pragma unroll
        for (int k0 = 0; k0 < KC; k0 += 8) {
            unsigned a0 = xs[(mw + r4    ) * PAD + k0 + c4    ];
            unsigned a1 = xs[(mw + r4 + 8) * PAD + k0 + c4    ];
            unsigned a2 = xs[(mw + r4    ) * PAD + k0 + c4 + 4];
            unsigned a3 = xs[(mw + r4 + 8) * PAD + k0 + c4 + 4];
#pragma unroll
            for (int nt = 0; nt < NT; nt++) {
                unsigned b0 = wt[(nt * 8 + r4) * PAD + k0 + c4    ];
                unsigned b1 = wt[(nt * 8 + r4) * PAD + k0 + c4 + 4];
                asm volatile(
                    "mma.sync.aligned.m16n8k8.row.col.f32.tf32.tf32.f32 "
                    "{%0,%1,%2,%3}, {%4,%5,%6,%7}, {%8,%9}, {%0,%1,%2,%3};"
                    : "+f"(acc[nt][0]), "+f"(acc[nt][1]),
                      "+f"(acc[nt][2]), "+f"(acc[nt][3])
                    : "r"(a0), "r"(a1), "r"(a2), "r"(a3), "r"(b0), "r"(b1));
            }
        }
        __syncthreads();
    }

    const int colb = c4 * 2;
    const int rowa = m0 + mw + r4;
#pragma unroll
    for (int nt = 0; nt < NT; nt++) {
        int n0 = nt * 8 + colb;
        if (rowa < M)
            *(float2*)&Y[rowa * TN + n0] = make_float2(acc[nt][0], acc[nt][1]);
        if (rowa + 8 < M)
            *(float2*)&Y[(rowa + 8) * TN + n0] = make_float2(acc[nt][2], acc[nt][3]);
    }
}

// ---------------------------------------------------------------------------
// Pull aggregation from buckets, one warp per node, unroll-4, 4 accumulators.
// ---------------------------------------------------------------------------
__global__ void k_gather128(int M)
{
    int w    = (blockIdx.x * blockDim.x + threadIdx.x) >> 5;
    int lane = threadIdx.x & 31;
    if (w >= M) return;
    const float4* __restrict__ H = (const float4*)g_h1;
    int cnt = min(g_fill[w], CAP);
    const int* __restrict__ bkt = &g_bkt[w * CAP];
    float dw = g_dinv[w];
    float4 v = H[w * 32 + lane];
    float cs = dw * dw;
    float4 a0 = make_float4(v.x * cs, v.y * cs, v.z * cs, v.w * cs);
    float4 a1 = make_float4(0.f, 0.f, 0.f, 0.f);
    float4 a2 = make_float4(0.f, 0.f, 0.f, 0.f);
    float4 a3 = make_float4(0.f, 0.f, 0.f, 0.f);
    int i = 0;
    for (; i + 4 <= cnt; i += 4) {
        int4  s4 = *(const int4*)&bkt[i];
        float c0 = g_dinv[s4.x] * dw;
        float c1 = g_dinv[s4.y] * dw;
        float c2 = g_dinv[s4.z] * dw;
        float c3 = g_dinv[s4.w] * dw;
        float4 v0 = H[s4.x * 32 + lane];
        float4 v1 = H[s4.y * 32 + lane];
        float4 v2 = H[s4.z * 32 + lane];
        float4 v3 = H[s4.w * 32 + lane];
        a0.x = fmaf(v0.x, c0, a0.x); a0.y = fmaf(v0.y, c0, a0.y);
        a0.z = fmaf(v0.z, c0, a0.z); a0.w = fmaf(v0.w, c0, a0.w);
        a1.x = fmaf(v1.x, c1, a1.x); a1.y = fmaf(v1.y, c1, a1.y);
        a1.z = fmaf(v1.z, c1, a1.z); a1.w = fmaf(v1.w, c1, a1.w);
        a2.x = fmaf(v2.x, c2, a2.x); a2.y = fmaf(v2.y, c2, a2.y);
        a2.z = fmaf(v2.z, c2, a2.z); a2.w = fmaf(v2.w, c2, a2.w);
        a3.x = fmaf(v3.x, c3, a3.x); a3.y = fmaf(v3.y, c3, a3.y);
        a3.z = fmaf(v3.z, c3, a3.z); a3.w = fmaf(v3.w, c3, a3.w);
    }
    for (; i < cnt; i++) {
        int s = bkt[i];
        float c = g_dinv[s] * dw;
        float4 v0 = H[s * 32 + lane];
        a0.x = fmaf(v0.x, c, a0.x); a0.y = fmaf(v0.y, c, a0.y);
        a0.z = fmaf(v0.z, c, a0.z); a0.w = fmaf(v0.w, c, a0.w);
    }
    a0.x += a1.x + a2.x + a3.x;
    a0.y += a1.y + a2.y + a3.y;
    a0.z += a1.z + a2.z + a3.z;
    a0.w += a1.w + a2.w + a3.w;
    ((float4*)g_agg1)[w * 32 + lane] = a0;
}

__global__ void k_gather64(const float* __restrict__ b2, float* __restrict__ outp, int M)
{
    int w    = (blockIdx.x * blockDim.x + threadIdx.x) >> 5;
    int lane = threadIdx.x & 31;
    if (w >= M) return;
    const float2* __restrict__ H = (const float2*)g_h2;
    int cnt = min(g_fill[w], CAP);
    const int* __restrict__ bkt = &g_bkt[w * CAP];
    float dw = g_dinv[w];
    float2 v = H[w * 32 + lane];
    float2 bb = ((const float2*)b2)[lane];
    float cs = dw * dw;
    float2 a0 = make_float2(fmaf(v.x, cs, bb.x), fmaf(v.y, cs, bb.y));
    float2 a1 = make_float2(0.f, 0.f);
    float2 a2 = make_float2(0.f, 0.f);
    float2 a3 = make_float2(0.f, 0.f);
    int i = 0;
    for (; i + 4 <= cnt; i += 4) {
        int4  s4 = *(const int4*)&bkt[i];
        float c0 = g_dinv[s4.x] * dw;
        float c1 = g_dinv[s4.y] * dw;
        float c2 = g_dinv[s4.z] * dw;
        float c3 = g_dinv[s4.w] * dw;
        float2 v0 = H[s4.x * 32 + lane];
        float2 v1 = H[s4.y * 32 + lane];
        float2 v2 = H[s4.z * 32 + lane];
        float2 v3 = H[s4.w * 32 + lane];
        a0.x = fmaf(v0.x, c0, a0.x); a0.y = fmaf(v0.y, c0, a0.y);
        a1.x = fmaf(v1.x, c1, a1.x); a1.y = fmaf(v1.y, c1, a1.y);
        a2.x = fmaf(v2.x, c2, a2.x); a2.y = fmaf(v2.y, c2, a2.y);
        a3.x = fmaf(v3.x, c3, a3.x); a3.y = fmaf(v3.y, c3, a3.y);
    }
    for (; i < cnt; i++) {
        int s = bkt[i];
        float c = g_dinv[s] * dw;
        float2 v0 = H[s * 32 + lane];
        a0.x = fmaf(v0.x, c, a0.x); a0.y = fmaf(v0.y, c, a0.y);
    }
    a0.x += a1.x + a2.x + a3.x;
    a0.y += a1.y + a2.y + a3.y;
    ((float2*)outp)[w * 32 + lane] = a0;
}

// ---------------------------------------------------------------------------
extern "C" void kernel_launch(void* const* d_in, const int* in_sizes, int n_in,
                              void* d_out, int out_size)
{
    const float* x  = (const float*)d_in[0];
    const void*  ei = d_in[1];
    const float* W1 = (const float*)d_in[2];
    const float* b1 = (const float*)d_in[3];
    const float* W2 = (const float*)d_in[4];
    const float* b2 = (const float*)d_in[5];
    float*       out = (float*)d_out;

    const int M = in_sizes[0] / INF;   // 50000
    const int E = in_sizes[1] / 2;     // 800000

    const int T = 256;

    // fork a side stream for the bucket-build chain (independent of GEMM1)
    cudaStream_t s1;
    cudaStreamCreateWithFlags(&s1, cudaStreamNonBlocking);
    cudaEvent_t evFork, evJoin;
    cudaEventCreateWithFlags(&evFork, cudaEventDisableTiming);
    cudaEventCreateWithFlags(&evJoin, cudaEventDisableTiming);

    cudaEventRecord(evFork, 0);
    cudaStreamWaitEvent(s1, evFork, 0);

    // --- chain B (s1): probe -> zero cursors -> fill buckets -> dinv ---
    k_probe    <<<1, 256, 0, s1>>>((const int*)ei, in_sizes[1]);
    k_zero_fill<<<(M + T - 1) / T, T, 0, s1>>>(M);
    k_fill     <<<(E + T - 1) / T, T, 0, s1>>>(ei, E);
    k_dinv     <<<(M + T - 1) / T, T, 0, s1>>>(M);
    cudaEventRecord(evJoin, s1);

    // --- chain A (default stream): layer-1 GEMM ---
    k_gemm_tf32<128, false><<<(M + 63) / 64, 128>>>(x, W1, b1, M);

    // join, then the dependent tail
    cudaStreamWaitEvent(0, evJoin, 0);
    k_gather128<<<(M * 32 + T - 1) / T, T>>>(M);
    k_gemm_tf32<64, true><<<(M + 63) / 64, 128>>>(nullptr, W2, b1, M);
    k_gather64<<<(M * 32 + T - 1) / T, T>>>(b2, out, M);
}

// round 9
// speedup vs baseline: 1.3745x; 1.3745x over previous
#include <cuda_runtime.h>
#include <cuda_bf16.h>

// ---------------------------------------------------------------------------
// 2-layer GCN. Pull aggregation via compact on-device CSR (precomputed edge
// coefficients), tf32 tensor-core GEMMs, parallel 3-phase scan, CSR chain
// overlapped with GEMM1 (fork/join). R7 structure + unroll-4 gathers +
// fused probe/zero + vectorized edge passes.
// ---------------------------------------------------------------------------

#define NMAX   50048
#define EMAX   800000
#define INF    128
#define OUTF   64
#define SCB    512

__device__ int   g_is64;
__device__ int   g_cnt [NMAX];
__device__ int   g_ptr [NMAX + 1];
__device__ int   g_fill[NMAX];
__device__ int   g_bsum[128];
__device__ int   g_boff[128];
__device__ int2  g_edge[EMAX];        // packed (src, __float_as_int(coeff))
__device__ float g_dinv[NMAX];
__device__ float g_h1  [NMAX * INF];
__device__ float g_agg1[NMAX * INF];
__device__ float g_h2  [NMAX * OUTF];

// ---------------------------------------------------------------------------
// block 0: dtype probe; blocks 1..: zero g_cnt
// ---------------------------------------------------------------------------
__global__ void k_probe_zero(const int* __restrict__ w32, int words, int M) {
    if (blockIdx.x == 0) {
        __shared__ int viol;
        if (threadIdx.x == 0) viol = 0;
        __syncthreads();
        int nchk = words / 2;
        if (nchk > 32768) nchk = 32768;
        int bad = 0;
        for (int i = threadIdx.x; i < nchk; i += blockDim.x)
            if (w32[2 * i + 1] != 0) bad = 1;
        if (bad) atomicOr(&viol, 1);
        __syncthreads();
        if (threadIdx.x == 0) g_is64 = (viol == 0) ? 1 : 0;
    } else {
        int i = (blockIdx.x - 1) * blockDim.x + threadIdx.x;
        if (i < M) g_cnt[i] = 0;
    }
}

// histogram of destinations, 2 edges per thread (16B/8B vector loads)
__global__ void k_count(const void* __restrict__ ei, int E) {
    int i  = blockIdx.x * blockDim.x + threadIdx.x;
    int n2 = E >> 1;
    if (g_is64) {
        const longlong2* p = (const longlong2*)((const long long*)ei + E);
        if (i < n2) {
            longlong2 v = p[i];
            atomicAdd(&g_cnt[(int)v.x], 1);
            atomicAdd(&g_cnt[(int)v.y], 1);
        }
        if (i == 0 && (E & 1))
            atomicAdd(&g_cnt[(int)((const long long*)ei)[E + E - 1]], 1);
    } else {
        const int2* p = (const int2*)((const int*)ei + E);
        if (i < n2) {
            int2 v = p[i];
            atomicAdd(&g_cnt[v.x], 1);
            atomicAdd(&g_cnt[v.y], 1);
        }
        if (i == 0 && (E & 1))
            atomicAdd(&g_cnt[((const int*)ei)[E + E - 1]], 1);
    }
}

// ---------------------------------------------------------------------------
// 3-phase parallel exclusive scan of g_cnt -> g_ptr/g_fill  (+ dinv)
// ---------------------------------------------------------------------------
__global__ void k_blocksum(int M) {
    __shared__ int ws[16];
    int t    = threadIdx.x;
    int node = blockIdx.x * SCB + t;
    int c = (node < M) ? g_cnt[node] : 0;
    if (node < M) g_dinv[node] = rsqrtf((float)(c + 1));
    int v = c;
#pragma unroll
    for (int o = 16; o; o >>= 1) v += __shfl_down_sync(0xffffffffu, v, o);
    if ((t & 31) == 0) ws[t >> 5] = v;
    __syncthreads();
    if (t < 16) {
        int u = ws[t];
#pragma unroll
        for (int o = 8; o; o >>= 1) u += __shfl_down_sync(0xffffu, u, o);
        if (t == 0) g_bsum[blockIdx.x] = u;
    }
}

__global__ void k_scanb(int nb, int M) {
    __shared__ int sh[128];
    int t = threadIdx.x;
    int v = (t < nb) ? g_bsum[t] : 0;
    sh[t] = v;
    __syncthreads();
    for (int o = 1; o < 128; o <<= 1) {
        int u = (t >= o) ? sh[t - o] : 0;
        __syncthreads();
        sh[t] += u;
        __syncthreads();
    }
    if (t < nb) g_boff[t] = sh[t] - v;
    if (t == nb - 1) g_ptr[M] = sh[t];
}

__global__ void k_scanc(int M) {
    __shared__ int sh[SCB];
    int t    = threadIdx.x;
    int node = blockIdx.x * SCB + t;
    int c = (node < M) ? g_cnt[node] : 0;
    sh[t] = c;
    __syncthreads();
    for (int o = 1; o < SCB; o <<= 1) {
        int u = (t >= o) ? sh[t - o] : 0;
        __syncthreads();
        sh[t] += u;
        __syncthreads();
    }
    if (node < M) {
        int excl = sh[t] - c + g_boff[blockIdx.x];
        g_ptr[node]  = excl;
        g_fill[node] = excl;
    }
}

// fill CSR, 2 edges per thread, reading edge_index directly
__global__ void k_fillcsr(const void* __restrict__ ei, int E) {
    int i  = blockIdx.x * blockDim.x + threadIdx.x;
    int n2 = E >> 1;
    int s0, d0, s1, d1;
    bool two = (i < n2);
    if (!two && !(i == n2 && (E & 1))) return;
    if (g_is64) {
        const long long* p = (const long long*)ei;
        if (two) {
            longlong2 sv = *(const longlong2*)&p[2 * i];
            longlong2 dv = *(const longlong2*)&p[E + 2 * i];
            s0 = (int)sv.x; s1 = (int)sv.y;
            d0 = (int)dv.x; d1 = (int)dv.y;
        } else {
            s0 = (int)p[E - 1]; d0 = (int)p[E + E - 1];
        }
    } else {
        const int* p = (const int*)ei;
        if (two) {
            int2 sv = *(const int2*)&p[2 * i];
            int2 dv = *(const int2*)&p[E + 2 * i];
            s0 = sv.x; s1 = sv.y;
            d0 = dv.x; d1 = dv.y;
        } else {
            s0 = p[E - 1]; d0 = p[E + E - 1];
        }
    }
    {
        float c = g_dinv[s0] * g_dinv[d0];
        int pos = atomicAdd(&g_fill[d0], 1);
        g_edge[pos] = make_int2(s0, __float_as_int(c));
    }
    if (two) {
        float c = g_dinv[s1] * g_dinv[d1];
        int pos = atomicAdd(&g_fill[d1], 1);
        g_edge[pos] = make_int2(s1, __float_as_int(c));
    }
}

// ---------------------------------------------------------------------------
// tf32 tensor-core GEMM:  Y[M,TN] = op(X)[M,128] * W[128,TN]
// ---------------------------------------------------------------------------
__device__ __forceinline__ unsigned f2tf(float f) {
    unsigned r;
    asm("cvt.rna.tf32.f32 %0, %1;" : "=r"(r) : "f"(f));
    return r;
}

template <int TN, bool PRELU>
__global__ void k_gemm_tf32(const float* __restrict__ Xin, const float* __restrict__ W,
                            const float* __restrict__ bias_in, int M)
{
    constexpr int KC  = 32;
    constexpr int NT  = TN / 8;
    constexpr int PAD = 36;

    const float* __restrict__ X = PRELU ? (const float*)g_agg1 : Xin;
    float* __restrict__ Y       = PRELU ? g_h2 : g_h1;

    __shared__ unsigned xs[64 * PAD];
    __shared__ unsigned wt[TN * PAD];

    const int tid  = threadIdx.x;
    const int lane = tid & 31;
    const int wid  = tid >> 5;
    const int m0   = blockIdx.x * 64;
    const int mw   = wid * 16;

    float acc[NT][4];
#pragma unroll
    for (int t = 0; t < NT; t++) { acc[t][0]=acc[t][1]=acc[t][2]=acc[t][3]=0.f; }

    const int r4 = lane >> 2;
    const int c4 = lane & 3;

    for (int kc = 0; kc < 128; kc += KC) {
#pragma unroll
        for (int i = 0; i < 4; i++) {
            int idx = tid + i * 128;
            int r   = idx >> 3;
            int kv  = (idx & 7) * 4;
            int row = m0 + r;
            float4 v = make_float4(0.f, 0.f, 0.f, 0.f);
            if (row < M) v = *(const float4*)&X[row * 128 + kc + kv];
            if (PRELU) {
                float4 b = *(const float4*)&bias_in[kc + kv];
                v.x = fmaxf(v.x + b.x, 0.f);
                v.y = fmaxf(v.y + b.y, 0.f);
                v.z = fmaxf(v.z + b.z, 0.f);
                v.w = fmaxf(v.w + b.w, 0.f);
            }
            uint4 u = make_uint4(f2tf(v.x), f2tf(v.y), f2tf(v.z), f2tf(v.w));
            *(uint4*)&xs[r * PAD + kv] = u;
        }
#pragma unroll
        for (int i = 0; i < (KC * TN / 4) / 128; i++) {
            int idx = tid + i * 128;
            int kk  = idx / (TN / 4);
            int n4  = (idx % (TN / 4)) * 4;
            float4 v = *(const float4*)&W[(kc + kk) * TN + n4];
            wt[(n4 + 0) * PAD + kk] = f2tf(v.x);
            wt[(n4 + 1) * PAD + kk] = f2tf(v.y);
            wt[(n4 + 2) * PAD + kk] = f2tf(v.z);
            wt[(n4 + 3) * PAD + kk] = f2tf(v.w);
        }
        __syncthreads();

#pragma unroll
        for (int k0 = 0; k0 < KC; k0 += 8) {
            unsigned a0 = xs[(mw + r4    ) * PAD + k0 + c4    ];
            unsigned a1 = xs[(mw + r4 + 8) * PAD + k0 + c4    ];
            unsigned a2 = xs[(mw + r4    ) * PAD + k0 + c4 + 4];
            unsigned a3 = xs[(mw + r4 + 8) * PAD + k0 + c4 + 4];
#pragma unroll
            for (int nt = 0; nt < NT; nt++) {
                unsigned b0 = wt[(nt * 8 + r4) * PAD + k0 + c4    ];
                unsigned b1 = wt[(nt * 8 + r4) * PAD + k0 + c4 + 4];
                asm volatile(
                    "mma.sync.aligned.m16n8k8.row.col.f32.tf32.tf32.f32 "
                    "{%0,%1,%2,%3}, {%4,%5,%6,%7}, {%8,%9}, {%0,%1,%2,%3};"
                    : "+f"(acc[nt][0]), "+f"(acc[nt][1]),
                      "+f"(acc[nt][2]), "+f"(acc[nt][3])
                    : "r"(a0), "r"(a1), "r"(a2), "r"(a3), "r"(b0), "r"(b1));
            }
        }
        __syncthreads();
    }

    const int colb = c4 * 2;
    const int rowa = m0 + mw + r4;
#pragma unroll
    for (int nt = 0; nt < NT; nt++) {
        int n0 = nt * 8 + colb;
        if (rowa < M)
            *(float2*)&Y[rowa * TN + n0] = make_float2(acc[nt][0], acc[nt][1]);
        if (rowa + 8 < M)
            *(float2*)&Y[(rowa + 8) * TN + n0] = make_float2(acc[nt][2], acc[nt][3]);
    }
}

// ---------------------------------------------------------------------------
// Pull aggregation, one warp per node, unroll-4, 4 independent accumulators.
// Coefficients precomputed in the edge list (no dependent dinv load).
// ---------------------------------------------------------------------------
__global__ void k_gather128(int M)
{
    int w    = (blockIdx.x * blockDim.x + threadIdx.x) >> 5;
    int lane = threadIdx.x & 31;
    if (w >= M) return;
    const float4* __restrict__ H = (const float4*)g_h1;
    int beg = g_ptr[w], end = g_ptr[w + 1];
    float cs = g_dinv[w]; cs *= cs;
    float4 v = H[w * 32 + lane];
    float4 a0 = make_float4(v.x * cs, v.y * cs, v.z * cs, v.w * cs);
    float4 a1 = make_float4(0.f, 0.f, 0.f, 0.f);
    float4 a2 = make_float4(0.f, 0.f, 0.f, 0.f);
    float4 a3 = make_float4(0.f, 0.f, 0.f, 0.f);
    int e = beg;
    for (; e + 4 <= end; e += 4) {
        int2 p0 = g_edge[e];
        int2 p1 = g_edge[e + 1];
        int2 p2 = g_edge[e + 2];
        int2 p3 = g_edge[e + 3];
        float c0 = __int_as_float(p0.y);
        float c1 = __int_as_float(p1.y);
        float c2 = __int_as_float(p2.y);
        float c3 = __int_as_float(p3.y);
        float4 v0 = H[p0.x * 32 + lane];
        float4 v1 = H[p1.x * 32 + lane];
        float4 v2 = H[p2.x * 32 + lane];
        float4 v3 = H[p3.x * 32 + lane];
        a0.x = fmaf(v0.x, c0, a0.x); a0.y = fmaf(v0.y, c0, a0.y);
        a0.z = fmaf(v0.z, c0, a0.z); a0.w = fmaf(v0.w, c0, a0.w);
        a1.x = fmaf(v1.x, c1, a1.x); a1.y = fmaf(v1.y, c1, a1.y);
        a1.z = fmaf(v1.z, c1, a1.z); a1.w = fmaf(v1.w, c1, a1.w);
        a2.x = fmaf(v2.x, c2, a2.x); a2.y = fmaf(v2.y, c2, a2.y);
        a2.z = fmaf(v2.z, c2, a2.z); a2.w = fmaf(v2.w, c2, a2.w);
        a3.x = fmaf(v3.x, c3, a3.x); a3.y = fmaf(v3.y, c3, a3.y);
        a3.z = fmaf(v3.z, c3, a3.z); a3.w = fmaf(v3.w, c3, a3.w);
    }
    for (; e < end; e++) {
        int2 p0 = g_edge[e];
        float c0 = __int_as_float(p0.y);
        float4 v0 = H[p0.x * 32 + lane];
        a0.x = fmaf(v0.x, c0, a0.x); a0.y = fmaf(v0.y, c0, a0.y);
        a0.z = fmaf(v0.z, c0, a0.z); a0.w = fmaf(v0.w, c0, a0.w);
    }
    a0.x += a1.x + a2.x + a3.x;
    a0.y += a1.y + a2.y + a3.y;
    a0.z += a1.z + a2.z + a3.z;
    a0.w += a1.w + a2.w + a3.w;
    ((float4*)g_agg1)[w * 32 + lane] = a0;
}

__global__ void k_gather64(const float* __restrict__ b2, float* __restrict__ outp, int M)
{
    int w    = (blockIdx.x * blockDim.x + threadIdx.x) >> 5;
    int lane = threadIdx.x & 31;
    if (w >= M) return;
    const float2* __restrict__ H = (const float2*)g_h2;
    int beg = g_ptr[w], end = g_ptr[w + 1];
    float cs = g_dinv[w]; cs *= cs;
    float2 v = H[w * 32 + lane];
    float2 bb = ((const float2*)b2)[lane];
    float2 a0 = make_float2(fmaf(v.x, cs, bb.x), fmaf(v.y, cs, bb.y));
    float2 a1 = make_float2(0.f, 0.f);
    float2 a2 = make_float2(0.f, 0.f);
    float2 a3 = make_float2(0.f, 0.f);
    int e = beg;
    for (; e + 4 <= end; e += 4) {
        int2 p0 = g_edge[e];
        int2 p1 = g_edge[e + 1];
        int2 p2 = g_edge[e + 2];
        int2 p3 = g_edge[e + 3];
        float c0 = __int_as_float(p0.y);
        float c1 = __int_as_float(p1.y);
        float c2 = __int_as_float(p2.y);
        float c3 = __int_as_float(p3.y);
        float2 v0 = H[p0.x * 32 + lane];
        float2 v1 = H[p1.x * 32 + lane];
        float2 v2 = H[p2.x * 32 + lane];
        float2 v3 = H[p3.x * 32 + lane];
        a0.x = fmaf(v0.x, c0, a0.x); a0.y = fmaf(v0.y, c0, a0.y);
        a1.x = fmaf(v1.x, c1, a1.x); a1.y = fmaf(v1.y, c1, a1.y);
        a2.x = fmaf(v2.x, c2, a2.x); a2.y = fmaf(v2.y, c2, a2.y);
        a3.x = fmaf(v3.x, c3, a3.x); a3.y = fmaf(v3.y, c3, a3.y);
    }
    for (; e < end; e++) {
        int2 p0 = g_edge[e];
        float c0 = __int_as_float(p0.y);
        float2 v0 = H[p0.x * 32 + lane];
        a0.x = fmaf(v0.x, c0, a0.x); a0.y = fmaf(v0.y, c0, a0.y);
    }
    a0.x += a1.x + a2.x + a3.x;
    a0.y += a1.y + a2.y + a3.y;
    ((float2*)outp)[w * 32 + lane] = a0;
}

// ---------------------------------------------------------------------------
extern "C" void kernel_launch(void* const* d_in, const int* in_sizes, int n_in,
                              void* d_out, int out_size)
{
    const float* x  = (const float*)d_in[0];
    const void*  ei = d_in[1];
    const float* W1 = (const float*)d_in[2];
    const float* b1 = (const float*)d_in[3];
    const float* W2 = (const float*)d_in[4];
    const float* b2 = (const float*)d_in[5];
    float*       out = (float*)d_out;

    const int M = in_sizes[0] / INF;   // 50000
    const int E = in_sizes[1] / 2;     // 800000

    const int T  = 256;
    const int NB = (M + SCB - 1) / SCB;
    const int E2 = (E >> 1) + 1;

    cudaStream_t s1;
    cudaStreamCreateWithFlags(&s1, cudaStreamNonBlocking);
    cudaEvent_t evFork, evJoin;
    cudaEventCreateWithFlags(&evFork, cudaEventDisableTiming);
    cudaEventCreateWithFlags(&evJoin, cudaEventDisableTiming);

    cudaEventRecord(evFork, 0);
    cudaStreamWaitEvent(s1, evFork, 0);

    // --- chain B (s1): probe+zero -> count -> scan(+dinv) -> fill ---
    k_probe_zero<<<1 + (M + T - 1) / T, T, 0, s1>>>((const int*)ei, in_sizes[1], M);
    k_count     <<<(E2 + T - 1) / T, T, 0, s1>>>(ei, E);
    k_blocksum  <<<NB, SCB, 0, s1>>>(M);
    k_scanb     <<<1, 128, 0, s1>>>(NB, M);
    k_scanc     <<<NB, SCB, 0, s1>>>(M);
    k_fillcsr   <<<(E2 + T - 1) / T, T, 0, s1>>>(ei, E);
    cudaEventRecord(evJoin, s1);

    // --- chain A (default stream): layer-1 GEMM ---
    k_gemm_tf32<128, false><<<(M + 63) / 64, 128>>>(x, W1, b1, M);

    cudaStreamWaitEvent(0, evJoin, 0);
    k_gather128<<<(M * 32 + T - 1) / T, T>>>(M);
    k_gemm_tf32<64, true><<<(M + 63) / 64, 128>>>(nullptr, W2, b1, M);
    k_gather64<<<(M * 32 + T - 1) / T, T>>>(b2, out, M);
}

// round 10
// speedup vs baseline: 1.4146x; 1.0292x over previous
#include <cuda_runtime.h>
#include <cuda_bf16.h>

// ---------------------------------------------------------------------------
// 2-layer GCN. Compact CSR pull aggregation (precomputed coefficients),
// tf32 tensor-core GEMMs, ONE-kernel decoupled-lookback scan, per-block
// inline dtype probe (no probe kernel), CSR chain overlapped with GEMM1.
// ---------------------------------------------------------------------------

#define NMAX   50048
#define EMAX   800000
#define INF    128
#define OUTF   64
#define SCB    512

__device__ int   g_cnt [NMAX];
__device__ int   g_ptr [NMAX + 1];
__device__ int   g_fill[NMAX];
__device__ volatile int g_ready[128];   // lookback: 0 = pending, sum+1 = done
__device__ int2  g_edge[EMAX];          // packed (src, __float_as_int(coeff))
__device__ float g_dinv[NMAX];
__device__ float g_h1  [NMAX * INF];
__device__ float g_agg1[NMAX * INF];
__device__ float g_h2  [NMAX * OUTF];

// ---------------------------------------------------------------------------
// block-local dtype probe: sample 256 odd 32-bit words; all zero <=> int64.
// Deterministic (same data -> same verdict in every block).
// ---------------------------------------------------------------------------
__device__ __forceinline__ int block_probe_is64(const int* __restrict__ w32) {
    __shared__ int s_is64;
    if (threadIdx.x == 0) s_is64 = 1;
    __syncthreads();
    if (threadIdx.x < 256) {
        if (w32[2 * threadIdx.x + 1] != 0) s_is64 = 0;  // racing writes of 0: fine
    }
    __syncthreads();
    return s_is64;
}

__global__ void k_zero(int M, int NB) {
    int i = blockIdx.x * blockDim.x + threadIdx.x;
    if (i < M)  g_cnt[i] = 0;
    if (i < NB) g_ready[i] = 0;
}

// histogram of destinations, 2 edges per thread
__global__ void k_count(const void* __restrict__ ei, int E) {
    int is64 = block_probe_is64((const int*)ei);
    int i  = blockIdx.x * blockDim.x + threadIdx.x;
    int n2 = E >> 1;
    if (is64) {
        const longlong2* p = (const longlong2*)((const long long*)ei + E);
        if (i < n2) {
            longlong2 v = p[i];
            atomicAdd(&g_cnt[(int)v.x], 1);
            atomicAdd(&g_cnt[(int)v.y], 1);
        }
        if (i == 0 && (E & 1))
            atomicAdd(&g_cnt[(int)((const long long*)ei)[E + E - 1]], 1);
    } else {
        const int2* p = (const int2*)((const int*)ei + E);
        if (i < n2) {
            int2 v = p[i];
            atomicAdd(&g_cnt[v.x], 1);
            atomicAdd(&g_cnt[v.y], 1);
        }
        if (i == 0 && (E & 1))
            atomicAdd(&g_cnt[((const int*)ei)[E + E - 1]], 1);
    }
}

// ---------------------------------------------------------------------------
// ONE-kernel exclusive scan (decoupled lookback) + dinv.
// Grid = NB (<=98) blocks of SCB threads: single wave, no deadlock.
// ---------------------------------------------------------------------------
__global__ void k_scan_lb(int M) {
    __shared__ int sh[SCB];
    __shared__ int s_off;
    const int t = threadIdx.x;
    const int b = blockIdx.x;
    const int node = b * SCB + t;

    int c = (node < M) ? g_cnt[node] : 0;
    if (node < M) g_dinv[node] = rsqrtf((float)(c + 1));   // +1 self loop

    // block-local inclusive scan
    sh[t] = c;
    __syncthreads();
    for (int o = 1; o < SCB; o <<= 1) {
        int u = (t >= o) ? sh[t - o] : 0;
        __syncthreads();
        sh[t] += u;
        __syncthreads();
    }
    int incl  = sh[t];
    int total = sh[SCB - 1];

    // publish block total (value+1 doubles as ready flag: single-word protocol)
    if (t == 0) {
        s_off = 0;
        g_ready[b] = total + 1;
    }
    __syncthreads();

    // lookback: thread t polls predecessor t (b <= 97 < SCB)
    if (t < b) {
        int v;
        while ((v = g_ready[t]) == 0) { }
        atomicAdd(&s_off, v - 1);
    }
    __syncthreads();

    int off = s_off;
    if (node < M) {
        int excl = off + incl - c;
        g_ptr[node]  = excl;
        g_fill[node] = excl;
        if (node == M - 1) g_ptr[M] = off + incl;
    }
}

// fill CSR, 2 edges per thread, inline probe
__global__ void k_fillcsr(const void* __restrict__ ei, int E) {
    int is64 = block_probe_is64((const int*)ei);
    int i  = blockIdx.x * blockDim.x + threadIdx.x;
    int n2 = E >> 1;
    int s0, d0, s1, d1;
    bool two = (i < n2);
    if (!two && !(i == n2 && (E & 1))) return;
    if (is64) {
        const long long* p = (const long long*)ei;
        if (two) {
            longlong2 sv = *(const longlong2*)&p[2 * i];
            longlong2 dv = *(const longlong2*)&p[E + 2 * i];
            s0 = (int)sv.x; s1 = (int)sv.y;
            d0 = (int)dv.x; d1 = (int)dv.y;
        } else {
            s0 = (int)p[E - 1]; d0 = (int)p[E + E - 1];
        }
    } else {
        const int* p = (const int*)ei;
        if (two) {
            int2 sv = *(const int2*)&p[2 * i];
            int2 dv = *(const int2*)&p[E + 2 * i];
            s0 = sv.x; s1 = sv.y;
            d0 = dv.x; d1 = dv.y;
        } else {
            s0 = p[E - 1]; d0 = p[E + E - 1];
        }
    }
    {
        float c = g_dinv[s0] * g_dinv[d0];
        int pos = atomicAdd(&g_fill[d0], 1);
        g_edge[pos] = make_int2(s0, __float_as_int(c));
    }
    if (two) {
        float c = g_dinv[s1] * g_dinv[d1];
        int pos = atomicAdd(&g_fill[d1], 1);
        g_edge[pos] = make_int2(s1, __float_as_int(c));
    }
}

// ---------------------------------------------------------------------------
// tf32 tensor-core GEMM:  Y[M,TN] = op(X)[M,128] * W[128,TN]
// ---------------------------------------------------------------------------
__device__ __forceinline__ unsigned f2tf(float f) {
    unsigned r;
    asm("cvt.rna.tf32.f32 %0, %1;" : "=r"(r) : "f"(f));
    return r;
}

template <int TN, bool PRELU>
__global__ void k_gemm_tf32(const float* __restrict__ Xin, const float* __restrict__ W,
                            const float* __restrict__ bias_in, int M)
{
    constexpr int KC  = 32;
    constexpr int NT  = TN / 8;
    constexpr int PAD = 36;

    const float* __restrict__ X = PRELU ? (const float*)g_agg1 : Xin;
    float* __restrict__ Y       = PRELU ? g_h2 : g_h1;

    __shared__ unsigned xs[64 * PAD];
    __shared__ unsigned wt[TN * PAD];

    const int tid  = threadIdx.x;
    const int lane = tid & 31;
    const int wid  = tid >> 5;
    const int m0   = blockIdx.x * 64;
    const int mw   = wid * 16;

    float acc[NT][4];
#pragma unroll
    for (int t = 0; t < NT; t++) { acc[t][0]=acc[t][1]=acc[t][2]=acc[t][3]=0.f; }

    const int r4 = lane >> 2;
    const int c4 = lane & 3;

    for (int kc = 0; kc < 128; kc += KC) {
#pragma unroll
        for (int i = 0; i < 4; i++) {
            int idx = tid + i * 128;
            int r   = idx >> 3;
            int kv  = (idx & 7) * 4;
            int row = m0 + r;
            float4 v = make_float4(0.f, 0.f, 0.f, 0.f);
            if (row < M) v = *(const float4*)&X[row * 128 + kc + kv];
            if (PRELU) {
                float4 b = *(const float4*)&bias_in[kc + kv];
                v.x = fmaxf(v.x + b.x, 0.f);
                v.y = fmaxf(v.y + b.y, 0.f);
                v.z = fmaxf(v.z + b.z, 0.f);
                v.w = fmaxf(v.w + b.w, 0.f);
            }
            uint4 u = make_uint4(f2tf(v.x), f2tf(v.y), f2tf(v.z), f2tf(v.w));
            *(uint4*)&xs[r * PAD + kv] = u;
        }
#pragma unroll
        for (int i = 0; i < (KC * TN / 4) / 128; i++) {
            int idx = tid + i * 128;
            int kk  = idx / (TN / 4);
            int n4  = (idx % (TN / 4)) * 4;
            float4 v = *(const float4*)&W[(kc + kk) * TN + n4];
            wt[(n4 + 0) * PAD + kk] = f2tf(v.x);
            wt[(n4 + 1) * PAD + kk] = f2tf(v.y);
            wt[(n4 + 2) * PAD + kk] = f2tf(v.z);
            wt[(n4 + 3) * PAD + kk] = f2tf(v.w);
        }
        __syncthreads();

#pragma unroll
        for (int k0 = 0; k0 < KC; k0 += 8) {
            unsigned a0 = xs[(mw + r4    ) * PAD + k0 + c4    ];
            unsigned a1 = xs[(mw + r4 + 8) * PAD + k0 + c4    ];
            unsigned a2 = xs[(mw + r4    ) * PAD + k0 + c4 + 4];
            unsigned a3 = xs[(mw + r4 + 8) * PAD + k0 + c4 + 4];
#pragma unroll
            for (int nt = 0; nt < NT; nt++) {
                unsigned b0 = wt[(nt * 8 + r4) * PAD + k0 + c4    ];
                unsigned b1 = wt[(nt * 8 + r4) * PAD + k0 + c4 + 4];
                asm volatile(
                    "mma.sync.aligned.m16n8k8.row.col.f32.tf32.tf32.f32 "
                    "{%0,%1,%2,%3}, {%4,%5,%6,%7}, {%8,%9}, {%0,%1,%2,%3};"
                    : "+f"(acc[nt][0]), "+f"(acc[nt][1]),
                      "+f"(acc[nt][2]), "+f"(acc[nt][3])
                    : "r"(a0), "r"(a1), "r"(a2), "r"(a3), "r"(b0), "r"(b1));
            }
        }
        __syncthreads();
    }

    const int colb = c4 * 2;
    const int rowa = m0 + mw + r4;
#pragma unroll
    for (int nt = 0; nt < NT; nt++) {
        int n0 = nt * 8 + colb;
        if (rowa < M)
            *(float2*)&Y[rowa * TN + n0] = make_float2(acc[nt][0], acc[nt][1]);
        if (rowa + 8 < M)
            *(float2*)&Y[(rowa + 8) * TN + n0] = make_float2(acc[nt][2], acc[nt][3]);
    }
}

// ---------------------------------------------------------------------------
// Pull aggregation, one warp per node, unroll-4, 4 independent accumulators.
// ---------------------------------------------------------------------------
__global__ void k_gather128(int M)
{
    int w    = (blockIdx.x * blockDim.x + threadIdx.x) >> 5;
    int lane = threadIdx.x & 31;
    if (w >= M) return;
    const float4* __restrict__ H = (const float4*)g_h1;
    int beg = g_ptr[w], end = g_ptr[w + 1];
    float cs = g_dinv[w]; cs *= cs;
    float4 v = H[w * 32 + lane];
    float4 a0 = make_float4(v.x * cs, v.y * cs, v.z * cs, v.w * cs);
    float4 a1 = make_float4(0.f, 0.f, 0.f, 0.f);
    float4 a2 = make_float4(0.f, 0.f, 0.f, 0.f);
    float4 a3 = make_float4(0.f, 0.f, 0.f, 0.f);
    int e = beg;
    for (; e + 4 <= end; e += 4) {
        int2 p0 = g_edge[e];
        int2 p1 = g_edge[e + 1];
        int2 p2 = g_edge[e + 2];
        int2 p3 = g_edge[e + 3];
        float c0 = __int_as_float(p0.y);
        float c1 = __int_as_float(p1.y);
        float c2 = __int_as_float(p2.y);
        float c3 = __int_as_float(p3.y);
        float4 v0 = H[p0.x * 32 + lane];
        float4 v1 = H[p1.x * 32 + lane];
        float4 v2 = H[p2.x * 32 + lane];
        float4 v3 = H[p3.x * 32 + lane];
        a0.x = fmaf(v0.x, c0, a0.x); a0.y = fmaf(v0.y, c0, a0.y);
        a0.z = fmaf(v0.z, c0, a0.z); a0.w = fmaf(v0.w, c0, a0.w);
        a1.x = fmaf(v1.x, c1, a1.x); a1.y = fmaf(v1.y, c1, a1.y);
        a1.z = fmaf(v1.z, c1, a1.z); a1.w = fmaf(v1.w, c1, a1.w);
        a2.x = fmaf(v2.x, c2, a2.x); a2.y = fmaf(v2.y, c2, a2.y);
        a2.z = fmaf(v2.z, c2, a2.z); a2.w = fmaf(v2.w, c2, a2.w);
        a3.x = fmaf(v3.x, c3, a3.x); a3.y = fmaf(v3.y, c3, a3.y);
        a3.z = fmaf(v3.z, c3, a3.z); a3.w = fmaf(v3.w, c3, a3.w);
    }
    for (; e < end; e++) {
        int2 p0 = g_edge[e];
        float c0 = __int_as_float(p0.y);
        float4 v0 = H[p0.x * 32 + lane];
        a0.x = fmaf(v0.x, c0, a0.x); a0.y = fmaf(v0.y, c0, a0.y);
        a0.z = fmaf(v0.z, c0, a0.z); a0.w = fmaf(v0.w, c0, a0.w);
    }
    a0.x += a1.x + a2.x + a3.x;
    a0.y += a1.y + a2.y + a3.y;
    a0.z += a1.z + a2.z + a3.z;
    a0.w += a1.w + a2.w + a3.w;
    ((float4*)g_agg1)[w * 32 + lane] = a0;
}

__global__ void k_gather64(const float* __restrict__ b2, float* __restrict__ outp, int M)
{
    int w    = (blockIdx.x * blockDim.x + threadIdx.x) >> 5;
    int lane = threadIdx.x & 31;
    if (w >= M) return;
    const float2* __restrict__ H = (const float2*)g_h2;
    int beg = g_ptr[w], end = g_ptr[w + 1];
    float cs = g_dinv[w]; cs *= cs;
    float2 v = H[w * 32 + lane];
    float2 bb = ((const float2*)b2)[lane];
    float2 a0 = make_float2(fmaf(v.x, cs, bb.x), fmaf(v.y, cs, bb.y));
    float2 a1 = make_float2(0.f, 0.f);
    float2 a2 = make_float2(0.f, 0.f);
    float2 a3 = make_float2(0.f, 0.f);
    int e = beg;
    for (; e + 4 <= end; e += 4) {
        int2 p0 = g_edge[e];
        int2 p1 = g_edge[e + 1];
        int2 p2 = g_edge[e + 2];
        int2 p3 = g_edge[e + 3];
        float c0 = __int_as_float(p0.y);
        float c1 = __int_as_float(p1.y);
        float c2 = __int_as_float(p2.y);
        float c3 = __int_as_float(p3.y);
        float2 v0 = H[p0.x * 32 + lane];
        float2 v1 = H[p1.x * 32 + lane];
        float2 v2 = H[p2.x * 32 + lane];
        float2 v3 = H[p3.x * 32 + lane];
        a0.x = fmaf(v0.x, c0, a0.x); a0.y = fmaf(v0.y, c0, a0.y);
        a1.x = fmaf(v1.x, c1, a1.x); a1.y = fmaf(v1.y, c1, a1.y);
        a2.x = fmaf(v2.x, c2, a2.x); a2.y = fmaf(v2.y, c2, a2.y);
        a3.x = fmaf(v3.x, c3, a3.x); a3.y = fmaf(v3.y, c3, a3.y);
    }
    for (; e < end; e++) {
        int2 p0 = g_edge[e];
        float c0 = __int_as_float(p0.y);
        float2 v0 = H[p0.x * 32 + lane];
        a0.x = fmaf(v0.x, c0, a0.x); a0.y = fmaf(v0.y, c0, a0.y);
    }
    a0.x += a1.x + a2.x + a3.x;
    a0.y += a1.y + a2.y + a3.y;
    ((float2*)outp)[w * 32 + lane] = a0;
}

// ---------------------------------------------------------------------------
extern "C" void kernel_launch(void* const* d_in, const int* in_sizes, int n_in,
                              void* d_out, int out_size)
{
    const float* x  = (const float*)d_in[0];
    const void*  ei = d_in[1];
    const float* W1 = (const float*)d_in[2];
    const float* b1 = (const float*)d_in[3];
    const float* W2 = (const float*)d_in[4];
    const float* b2 = (const float*)d_in[5];
    float*       out = (float*)d_out;

    const int M = in_sizes[0] / INF;   // 50000
    const int E = in_sizes[1] / 2;     // 800000

    const int T  = 256;
    const int NB = (M + SCB - 1) / SCB;   // <= 98
    const int E2 = (E >> 1) + 1;

    cudaStream_t s1;
    cudaStreamCreateWithFlags(&s1, cudaStreamNonBlocking);
    cudaEvent_t evFork, evJoin;
    cudaEventCreateWithFlags(&evFork, cudaEventDisableTiming);
    cudaEventCreateWithFlags(&evJoin, cudaEventDisableTiming);

    cudaEventRecord(evFork, 0);
    cudaStreamWaitEvent(s1, evFork, 0);

    // --- chain B (s1): zero -> count -> lookback-scan(+dinv) -> fill ---
    k_zero   <<<(M + T - 1) / T, T, 0, s1>>>(M, NB);
    k_count  <<<(E2 + T - 1) / T, T, 0, s1>>>(ei, E);
    k_scan_lb<<<NB, SCB, 0, s1>>>(M);
    k_fillcsr<<<(E2 + T - 1) / T, T, 0, s1>>>(ei, E);
    cudaEventRecord(evJoin, s1);

    // --- chain A (default stream): layer-1 GEMM ---
    k_gemm_tf32<128, false><<<(M + 63) / 64, 128>>>(x, W1, b1, M);

    cudaStreamWaitEvent(0, evJoin, 0);
    k_gather128<<<(M * 32 + T - 1) / T, T>>>(M);
    k_gemm_tf32<64, true><<<(M + 63) / 64, 128>>>(nullptr, W2, b1, M);
    k_gather64<<<(M * 32 + T - 1) / T, T>>>(b2, out, M);
}